// round 6
// baseline (speedup 1.0000x reference)
#include <cuda_runtime.h>

#define NB 4
#define NH 16
#define SEQ 2048
#define DIM 1024
#define HD 64
#define SCALE 0.03125f   // 1/sqrt(1024)

typedef unsigned int u32;

// Scratch (allocation-free rule: __device__ globals)
__device__ float g_linv[NB * NH * SEQ];
__device__ float g_att[(size_t)NB * SEQ * DIM];

// ---------------------------------------------------------------------------
// Low-level helpers (portable sm_80+ PTX)
// ---------------------------------------------------------------------------
__device__ __forceinline__ u32 f2tf(float x) {
    u32 r; asm("cvt.rna.tf32.f32 %0, %1;" : "=r"(r) : "f"(x)); return r;
}
__device__ __forceinline__ u32 prmt_hi(u32 a, u32 b) {   // {lo16=a.hi16, hi16=b.hi16}
    u32 r; asm("prmt.b32 %0, %1, %2, 0x7632;" : "=r"(r) : "r"(a), "r"(b)); return r;
}
__device__ __forceinline__ u32 bf16x2_rn(float hi, float lo) {
    u32 r; asm("cvt.rn.bf16x2.f32 %0, %1, %2;" : "=r"(r) : "f"(hi), "f"(lo)); return r;
}
__device__ __forceinline__ float truncb(float x) {       // exact bf16 truncation
    return __uint_as_float(__float_as_uint(x) & 0xFFFF0000u);
}

// m16n8k8 tf32 mma
__device__ __forceinline__ void mma8(float c[4], uint4 a, uint2 b) {
    asm volatile(
        "mma.sync.aligned.m16n8k8.row.col.f32.tf32.tf32.f32 "
        "{%0,%1,%2,%3}, {%4,%5,%6,%7}, {%8,%9}, {%0,%1,%2,%3};"
        : "+f"(c[0]), "+f"(c[1]), "+f"(c[2]), "+f"(c[3])
        : "r"(a.x), "r"(a.y), "r"(a.z), "r"(a.w), "r"(b.x), "r"(b.y));
}
// m16n8k16 bf16 mma
__device__ __forceinline__ void mma16(float c[4], uint4 a, uint2 b) {
    asm volatile(
        "mma.sync.aligned.m16n8k16.row.col.f32.bf16.bf16.f32 "
        "{%0,%1,%2,%3}, {%4,%5,%6,%7}, {%8,%9}, {%0,%1,%2,%3};"
        : "+f"(c[0]), "+f"(c[1]), "+f"(c[2]), "+f"(c[3])
        : "r"(a.x), "r"(a.y), "r"(a.z), "r"(a.w), "r"(b.x), "r"(b.y));
}

// ---------------------------------------------------------------------------
// tf32 fragment packs
// A-pack: [ks][mt][lane] uint4; B-pack: [ks][nt][lane] uint2
// ---------------------------------------------------------------------------
template<int MT>
__device__ __forceinline__ uint4 ldAf(const u32* A, int ks, int mt, int lane) {
    return *(const uint4*)(A + ((size_t)((ks * MT + mt) * 32 + lane)) * 4);
}
template<int NT>
__device__ __forceinline__ uint2 ldBf(const u32* B, int ks, int nt, int lane) {
    return *(const uint2*)(B + ((size_t)((ks * NT + nt) * 32 + lane)) * 2);
}
template<int MT>
__device__ __forceinline__ void stA4(u32* A, int r, int c4, float4 v) {
    int base = (((c4 >> 3) * MT + (r >> 4)) * 32 + ((r & 7) << 2)) * 4
             + (((r >> 3) & 1) | (((c4 >> 2) & 1) << 1));
    A[base + 0]  = f2tf(v.x);
    A[base + 4]  = f2tf(v.y);
    A[base + 8]  = f2tf(v.z);
    A[base + 12] = f2tf(v.w);
}
template<int NT>
__device__ __forceinline__ void stB4_nk(u32* B, int n, int c4, float4 v) {
    int base = (((c4 >> 3) * NT + (n >> 3)) * 32 + ((n & 7) << 2)) * 2
             + ((c4 >> 2) & 1);
    B[base + 0] = f2tf(v.x);
    B[base + 2] = f2tf(v.y);
    B[base + 4] = f2tf(v.z);
    B[base + 6] = f2tf(v.w);
}

// ---------------------------------------------------------------------------
// bf16 fragment packs (m16n8k16).  B-pack padded: stride 33 lane-pairs.
// ---------------------------------------------------------------------------
__device__ __forceinline__ uint4 ldA16(const u32* A, int ks, int mt, int lane) {
    return *(const uint4*)(A + ((size_t)((ks * 8 + mt) * 32 + lane)) * 4);
}
template<int NT>
__device__ __forceinline__ uint2 ldB16(const u32* B, int ks, int nt, int lane) {
    return *(const uint2*)(B + ((size_t)((ks * NT + nt) * 33 + lane)) * 2);
}
__device__ __forceinline__ void stA16_rn(u32* A, int r, int c4, float4 v) {
    int ks = c4 >> 4, kkb = c4 & 15;
    const float* f = &v.x;
#pragma unroll
    for (int p = 0; p < 2; p++) {
        int kk = kkb + 2 * p;
        int c = (kk & 7) >> 1, slot = ((r >> 3) & 1) | ((kk >> 3) << 1);
        int idx = ((ks * 8 + (r >> 4)) * 32 + ((r & 7) << 2) + c) * 4 + slot;
        A[idx] = bf16x2_rn(f[2 * p + 1], f[2 * p]);
    }
}
template<int NT>
__device__ __forceinline__ void stB16_rn(u32* B, int n, int c4, float4 v) {
    int ks = c4 >> 4, kkb = c4 & 15;
    const float* f = &v.x;
#pragma unroll
    for (int p = 0; p < 2; p++) {
        int kk = kkb + 2 * p;
        int c = (kk & 7) >> 1, breg = kk >> 3;
        int idx = ((ks * NT + (n >> 3)) * 33 + ((n & 7) << 2) + c) * 2 + breg;
        B[idx] = bf16x2_rn(f[2 * p + 1], f[2 * p]);
    }
}

// ---------------------------------------------------------------------------
// Kernel 1: l[k] = sum_q exp(s[q,k]); store 1/l. (unchanged from round 5)
// ---------------------------------------------------------------------------
__global__ void __launch_bounds__(256) k1_colsum(const float* __restrict__ Qg,
                                                 const float* __restrict__ Kg) {
    extern __shared__ u32 smu[];
    u32* Ka = smu;                       // 4096 u32
    u32* Qb = smu + 4096;                // 4224 u32
    float* colsum = (float*)(smu + 8320);
    int tid = threadIdx.x, lane = tid & 31, w = tid >> 5;
    int wm = w >> 2, wn = w & 3;
    int b = blockIdx.z, h = blockIdx.y, k0 = blockIdx.x << 7;

    const float* Kb = Kg + ((size_t)b * SEQ + k0) * DIM + h * HD;
    const float* Qbase = Qg + (size_t)b * SEQ * DIM + h * HD;

    int rb = tid >> 4, c4 = (tid & 15) << 2;
#pragma unroll
    for (int it = 0; it < 8; it++) {
        int r = rb + (it << 4);
        stA16_rn(Ka, r, c4, *(const float4*)(Kb + (size_t)r * DIM + c4));
    }
    if (tid < 128) colsum[tid] = 0.f;

    float sume[4][2];
#pragma unroll
    for (int i = 0; i < 4; i++) { sume[i][0] = 0.f; sume[i][1] = 0.f; }

    for (int q0 = 0; q0 < SEQ; q0 += 128) {
        __syncthreads();
#pragma unroll
        for (int it = 0; it < 8; it++) {
            int n = rb + (it << 4);
            stB16_rn<16>(Qb, n, c4,
                         *(const float4*)(Qbase + (size_t)(q0 + n) * DIM + c4));
        }
        __syncthreads();

        float acc[4][4][4];
#pragma unroll
        for (int i = 0; i < 4; i++)
#pragma unroll
            for (int j = 0; j < 4; j++)
#pragma unroll
                for (int t = 0; t < 4; t++) acc[i][j][t] = 0.f;

#pragma unroll
        for (int ks = 0; ks < 4; ks++) {
            uint4 af[4]; uint2 bf[4];
#pragma unroll
            for (int i = 0; i < 4; i++) af[i] = ldA16(Ka, ks, wm * 4 + i, lane);
#pragma unroll
            for (int j = 0; j < 4; j++) bf[j] = ldB16<16>(Qb, ks, wn * 4 + j, lane);
#pragma unroll
            for (int i = 0; i < 4; i++)
#pragma unroll
                for (int j = 0; j < 4; j++) mma16(acc[i][j], af[i], bf[j]);
        }
#pragma unroll
        for (int i = 0; i < 4; i++)
#pragma unroll
            for (int j = 0; j < 4; j++) {
                sume[i][0] += __expf(acc[i][j][0] * SCALE) + __expf(acc[i][j][1] * SCALE);
                sume[i][1] += __expf(acc[i][j][2] * SCALE) + __expf(acc[i][j][3] * SCALE);
            }
    }

#pragma unroll
    for (int i = 0; i < 4; i++)
#pragma unroll
        for (int hh = 0; hh < 2; hh++) {
            float v = sume[i][hh];
            v += __shfl_xor_sync(0xffffffffu, v, 1);
            v += __shfl_xor_sync(0xffffffffu, v, 2);
            if ((lane & 3) == 0)
                atomicAdd(&colsum[wm * 64 + i * 16 + (lane >> 2) + hh * 8], v);
        }
    __syncthreads();
    if (tid < 128)
        g_linv[((size_t)b * NH + h) * SEQ + k0 + tid] = 1.0f / colsum[tid];
}

// ---------------------------------------------------------------------------
// k2 helpers: convert+store K tile and V tile into packs
// ---------------------------------------------------------------------------
__device__ __forceinline__ void k2_store_K(u32* Kd, const float4 kreg[8],
                                           int rb, int c4) {
#pragma unroll
    for (int it = 0; it < 8; it++)
        stB4_nk<16>(Kd, rb + (it << 4), c4, kreg[it]);
}
__device__ __forceinline__ void k2_store_V(u32* Vhd, u32* Vld,
                                           const float4 vreg[8], const float rlreg[8],
                                           int rb, int c4, int lane) {
#pragma unroll
    for (int it = 0; it < 8; it++) {
        int kt = rb + (it << 4);
        float rl = rlreg[it];
        float4 v = vreg[it];
        v.x *= rl; v.y *= rl; v.z *= rl; v.w *= rl;
        float4 oth;
        oth.x = __shfl_xor_sync(0xffffffffu, v.x, 16);
        oth.y = __shfl_xor_sync(0xffffffffu, v.y, 16);
        oth.z = __shfl_xor_sync(0xffffffffu, v.z, 16);
        oth.w = __shfl_xor_sync(0xffffffffu, v.w, 16);
        float4 ve, vo;
        if (lane & 16) { ve = oth; vo = v; } else { ve = v; vo = oth; }
        int ke = kt & ~1;
        int ksv = ke >> 4, kk = ke & 15;
        int c = (kk & 7) >> 1, breg = kk >> 3;
        const float* pe = &ve.x; const float* po = &vo.x;
#pragma unroll
        for (int j = 0; j < 4; j++) {
            int d = c4 + j;
            int idx = ((ksv * 8 + (d >> 3)) * 33 + ((d & 7) << 2) + c) * 2 + breg;
            float a = pe[j], bb = po[j];
            if (!(lane & 16))
                Vhd[idx] = prmt_hi(__float_as_uint(a), __float_as_uint(bb));
            else
                Vld[idx] = bf16x2_rn(bb - truncb(bb), a - truncb(a));
        }
    }
}

// ---------------------------------------------------------------------------
// Kernel 2: out[q,:] = sum_k exp(s[q,k]) * (linv[k]*v[k,:]).
// Double-buffered K/Vh/Vl packs, register-prefetch pipeline, 1 sync/tile.
// gemm1 tf32 (warp = 16q x 128k), P converted in regs to bf16 hi/lo,
// gemm2 3-pass bf16 (Ph*Vh + Ph*Vl + Pl*Vh). Numerics identical to round 5.
// ---------------------------------------------------------------------------
__global__ void __launch_bounds__(256) k2_attnv(const float* __restrict__ Qg,
                                                const float* __restrict__ Kg,
                                                const float* __restrict__ Vg) {
    extern __shared__ u32 smu[];
    u32* Qa = smu;                 // tf32 A-pack 128q x 64d : 8192
    // double buffers
    u32* KpB[2] = { smu + 8192,  smu + 16384 };   // tf32 B-pack 8192 each
    u32* VhB[2] = { smu + 24576, smu + 33024 };   // bf16 B-pack 4224 each
    u32* VlB[2] = { smu + 28800, smu + 37248 };   // bf16 B-pack 4224 each
    // total 41472 u32 = 165888 B

    int tid = threadIdx.x, lane = tid & 31, w = tid >> 5;
    int b = blockIdx.z, h = blockIdx.y, q0 = blockIdx.x << 7;

    const float* Qb = Qg + ((size_t)b * SEQ + q0) * DIM + h * HD;
    const float* Kbase = Kg + (size_t)b * SEQ * DIM + h * HD;
    const float* Vbase = Vg + (size_t)b * SEQ * DIM + h * HD;
    const float* linv = g_linv + ((size_t)b * NH + h) * SEQ;

    int rb = tid >> 4, c4 = (tid & 15) << 2;
#pragma unroll
    for (int it = 0; it < 8; it++) {
        int r = rb + (it << 4);
        stA4<8>(Qa, r, c4, *(const float4*)(Qb + (size_t)r * DIM + c4));
    }

    float4 kreg[8], vreg[8];
    float rlreg[8];

    // prologue: tile 0 into buffer 0
#pragma unroll
    for (int it = 0; it < 8; it++) {
        int n = rb + (it << 4);
        kreg[it] = *(const float4*)(Kbase + (size_t)n * DIM + c4);
        vreg[it] = *(const float4*)(Vbase + (size_t)n * DIM + c4);
        rlreg[it] = __ldg(linv + n);
    }
    k2_store_K(KpB[0], kreg, rb, c4);
    k2_store_V(VhB[0], VlB[0], vreg, rlreg, rb, c4, lane);
    __syncthreads();

    float o[8][4];
#pragma unroll
    for (int nt = 0; nt < 8; nt++)
#pragma unroll
        for (int t = 0; t < 4; t++) o[nt][t] = 0.f;

    for (int t = 0; t < 16; t++) {
        int cur = t & 1, nxt = cur ^ 1;
        const u32* Kc = KpB[cur];
        const u32* Vhc = VhB[cur];
        const u32* Vlc = VlB[cur];
        bool hn = (t < 15);
        int k0n = (t + 1) << 7;

        // prefetch K(t+1) — latency hidden by gemm1
        if (hn) {
#pragma unroll
            for (int it = 0; it < 8; it++) {
                int n = rb + (it << 4);
                kreg[it] = *(const float4*)(Kbase + (size_t)(k0n + n) * DIM + c4);
            }
        }

        // gemm1 (tf32): warp w -> q rows [16w,16w+16), all 128 k-cols
        float acc[16][4];
#pragma unroll
        for (int nt = 0; nt < 16; nt++)
#pragma unroll
            for (int tt = 0; tt < 4; tt++) acc[nt][tt] = 0.f;
#pragma unroll
        for (int ks = 0; ks < 8; ks++) {
            uint4 a = ldAf<8>(Qa, ks, w, lane);
#pragma unroll
            for (int nt = 0; nt < 16; nt++) {
                uint2 bf = ldBf<16>(Kc, ks, nt, lane);
                mma8(acc[nt], a, bf);
            }
        }

        // stage K(t+1) into the other buffer (data ready by now)
        if (hn) k2_store_K(KpB[nxt], kreg, rb, c4);

        // prefetch V(t+1) — latency hidden by gemm2
        if (hn) {
#pragma unroll
            for (int it = 0; it < 8; it++) {
                int n = rb + (it << 4);
                vreg[it] = *(const float4*)(Vbase + (size_t)(k0n + n) * DIM + c4);
                rlreg[it] = __ldg(linv + k0n + n);
            }
        }

        // exp -> bf16 hi/lo A-frags in registers; gemm2 immediately
#pragma unroll
        for (int ks2 = 0; ks2 < 8; ks2++) {
            float e0 = __expf(acc[2 * ks2][0] * SCALE);
            float e1 = __expf(acc[2 * ks2][1] * SCALE);
            float e2 = __expf(acc[2 * ks2][2] * SCALE);
            float e3 = __expf(acc[2 * ks2][3] * SCALE);
            float e4 = __expf(acc[2 * ks2 + 1][0] * SCALE);
            float e5 = __expf(acc[2 * ks2 + 1][1] * SCALE);
            float e6 = __expf(acc[2 * ks2 + 1][2] * SCALE);
            float e7 = __expf(acc[2 * ks2 + 1][3] * SCALE);
            uint4 ah, al;
            ah.x = prmt_hi(__float_as_uint(e0), __float_as_uint(e1));
            ah.y = prmt_hi(__float_as_uint(e2), __float_as_uint(e3));
            ah.z = prmt_hi(__float_as_uint(e4), __float_as_uint(e5));
            ah.w = prmt_hi(__float_as_uint(e6), __float_as_uint(e7));
            al.x = bf16x2_rn(e1 - truncb(e1), e0 - truncb(e0));
            al.y = bf16x2_rn(e3 - truncb(e3), e2 - truncb(e2));
            al.z = bf16x2_rn(e5 - truncb(e5), e4 - truncb(e4));
            al.w = bf16x2_rn(e7 - truncb(e7), e6 - truncb(e6));
#pragma unroll
            for (int nt = 0; nt < 8; nt++) {
                uint2 bh = ldB16<8>(Vhc, ks2, nt, lane);
                uint2 bl = ldB16<8>(Vlc, ks2, nt, lane);
                mma16(o[nt], ah, bh);
                mma16(o[nt], ah, bl);
                mma16(o[nt], al, bh);
            }
        }

        // stage V(t+1)
        if (hn) k2_store_V(VhB[nxt], VlB[nxt], vreg, rlreg, rb, c4, lane);

        __syncthreads();
    }

    int r = lane >> 2, c2 = (lane & 3) << 1;
    float* obase = g_att + ((size_t)b * SEQ + q0 + 16 * w + r) * DIM + h * HD;
#pragma unroll
    for (int nt = 0; nt < 8; nt++) {
        *(float2*)(obase + nt * 8 + c2) = make_float2(o[nt][0], o[nt][1]);
        *(float2*)(obase + (size_t)8 * DIM + nt * 8 + c2) =
            make_float2(o[nt][2], o[nt][3]);
    }
}

// ---------------------------------------------------------------------------
// Kernel 3: out = g_att @ W^T + b.  bf16 3-pass split. (unchanged)
// ---------------------------------------------------------------------------
__global__ void __launch_bounds__(256, 2) k3_linear(const float* __restrict__ Wg,
                                                    const float* __restrict__ bg,
                                                    float* __restrict__ Og) {
    extern __shared__ u32 smu[];
    u32* Xh = smu;             // 4096
    u32* Xl = smu + 4096;      // 4096
    u32* Wh = smu + 8192;      // 4224
    u32* Wl = smu + 12416;     // 4224

    int tid = threadIdx.x, lane = tid & 31, w = tid >> 5;
    int wm = w >> 2, wn = w & 3;
    int n0 = blockIdx.x << 7, m0 = blockIdx.y << 7;

    float acc[4][4][4];
#pragma unroll
    for (int i = 0; i < 4; i++)
#pragma unroll
        for (int j = 0; j < 4; j++)
#pragma unroll
            for (int t = 0; t < 4; t++) acc[i][j][t] = 0.f;

    int rb = tid >> 4, c4 = (tid & 15) << 2;
    for (int d0 = 0; d0 < DIM; d0 += 64) {
        __syncthreads();
#pragma unroll
        for (int it = 0; it < 8; it++) {
            int r = rb + (it << 4);
            float4 x = *(const float4*)(g_att + (size_t)(m0 + r) * DIM + d0 + c4);
            float4 wv = *(const float4*)(Wg + (size_t)(n0 + r) * DIM + d0 + c4);
            const float* xf = &x.x; const float* wf = &wv.x;
            int ks = c4 >> 4, kkb = c4 & 15;
#pragma unroll
            for (int p = 0; p < 2; p++) {
                int kk = kkb + 2 * p;
                int c = (kk & 7) >> 1;
                {
                    int slot = ((r >> 3) & 1) | ((kk >> 3) << 1);
                    int idx = ((ks * 8 + (r >> 4)) * 32 + ((r & 7) << 2) + c) * 4 + slot;
                    float a = xf[2 * p], bb = xf[2 * p + 1];
                    Xh[idx] = prmt_hi(__float_as_uint(a), __float_as_uint(bb));
                    Xl[idx] = bf16x2_rn(bb - truncb(bb), a - truncb(a));
                }
                {
                    int breg = kk >> 3;
                    int idx = ((ks * 16 + (r >> 3)) * 33 + ((r & 7) << 2) + c) * 2 + breg;
                    float a = wf[2 * p], bb = wf[2 * p + 1];
                    Wh[idx] = prmt_hi(__float_as_uint(a), __float_as_uint(bb));
                    Wl[idx] = bf16x2_rn(bb - truncb(bb), a - truncb(a));
                }
            }
        }
        __syncthreads();

#pragma unroll
        for (int ks = 0; ks < 4; ks++) {
            uint4 ah[4], al[4]; uint2 bh[4], bl[4];
#pragma unroll
            for (int i = 0; i < 4; i++) {
                ah[i] = ldA16(Xh, ks, wm * 4 + i, lane);
                al[i] = ldA16(Xl, ks, wm * 4 + i, lane);
            }
#pragma unroll
            for (int j = 0; j < 4; j++) {
                bh[j] = ldB16<16>(Wh, ks, wn * 4 + j, lane);
                bl[j] = ldB16<16>(Wl, ks, wn * 4 + j, lane);
            }
#pragma unroll
            for (int i = 0; i < 4; i++)
#pragma unroll
                for (int j = 0; j < 4; j++) {
                    mma16(acc[i][j], ah[i], bh[j]);
                    mma16(acc[i][j], ah[i], bl[j]);
                    mma16(acc[i][j], al[i], bh[j]);
                }
        }
    }

#pragma unroll
    for (int i = 0; i < 4; i++)
#pragma unroll
        for (int j = 0; j < 4; j++) {
            int r = wm * 64 + i * 16 + (lane >> 2);
            int n = wn * 32 + j * 8 + ((lane & 3) << 1);
            float2 bb = *(const float2*)(bg + n0 + n);
            float* p = Og + (size_t)(m0 + r) * DIM + n0 + n;
            *(float2*)p = make_float2(acc[i][j][0] + bb.x, acc[i][j][1] + bb.y);
            *(float2*)(p + (size_t)8 * DIM) =
                make_float2(acc[i][j][2] + bb.x, acc[i][j][3] + bb.y);
        }
}

// ---------------------------------------------------------------------------

extern "C" void kernel_launch(void* const* d_in, const int* in_sizes, int n_in,
                              void* d_out, int out_size) {
    const float* Q = (const float*)d_in[0];
    const float* K = (const float*)d_in[1];
    const float* V = (const float*)d_in[2];
    const float* W = (const float*)d_in[3];
    const float* bias = (const float*)d_in[4];
    float* out = (float*)d_out;
    (void)in_sizes; (void)n_in; (void)out_size;

    const int smem1 = (4096 + 4224 + 128) * 4;   // 33792
    const int smem2 = 41472 * 4;                 // 165888
    const int smem3 = 16640 * 4;                 // 66560

    cudaFuncSetAttribute(k1_colsum, cudaFuncAttributeMaxDynamicSharedMemorySize, smem1);
    cudaFuncSetAttribute(k2_attnv,  cudaFuncAttributeMaxDynamicSharedMemorySize, smem2);
    cudaFuncSetAttribute(k3_linear, cudaFuncAttributeMaxDynamicSharedMemorySize, smem3);

    dim3 gAttn(SEQ / 128, NH, NB);          // 1024 CTAs
    k1_colsum<<<gAttn, 256, smem1>>>(Q, K);
    k2_attnv<<<gAttn, 256, smem2>>>(Q, K, V);

    dim3 gLin(DIM / 128, (NB * SEQ) / 128); // 512 CTAs
    k3_linear<<<gLin, 256, smem3>>>(W, bias, out);
}